// round 8
// baseline (speedup 1.0000x reference)
#include <cuda_runtime.h>
#include <limits.h>

#define PRE 2000
#define POST 300
#define IOU_T 0.55f
#define T 512
#define NC 5
#define SLOTS 4
#define OVF (SLOTS + 1)
#define NWORD 63
#define ICH 250
#define FULL 0xffffffffu

// Inter-kernel scratch (device globals: allocation-free per harness rules)
__device__ float g_box[PRE * 4];
__device__ float g_score[PRE];
__device__ float g_cls[PRE];
__device__ float g_key[PRE];
__device__ int   g_rank[PRE];

// Exact reference IoU decision: det box (b*, a1) vs cluster mean (m*, a2).
__device__ __forceinline__ bool iou_match(
    float bx1, float by1, float bx2, float by2, float a1,
    float mx, float my, float mz, float mw, float a2)
{
    const float lx = fmaxf(bx1, mx);
    const float ly = fmaxf(by1, my);
    const float rx = fminf(bx2, mz);
    const float ry = fminf(by2, mw);
    const float w  = fmaxf(__fsub_rn(rx, lx), 0.0f);
    const float h  = fmaxf(__fsub_rn(ry, ly), 0.0f);
    const float inter = __fmul_rn(w, h);
    if (inter <= 0.0f) return false;
    const float uni = __fsub_rn(__fadd_rn(a1, a2), inter);  // >= inter > 0
    return __fdiv_rn(inter, uni) > IOU_T;
}

// ---------------------------------------------------------------------------
// Kernel 1: epoch-based WBF (dense class-ordered state; single-warp phase 2).
// Every det starts as a singleton cluster. Phase 1 precomputes each det's
// matching creators vs singleton means. Phase 2 (warp 0 only, barrier-free):
// pick earliest candidate with an alive match, merge it, repair only the
// affected class's match lists vs the one updated mean. One epoch per merge.
// ---------------------------------------------------------------------------
__global__ void __launch_bounds__(T, 1)
wbf_scan(const float* __restrict__ x) {
    extern __shared__ float smem[];
    float4* d_boxv  = (float4*)smem;            // PRE dense raw det boxes
    float4* d_mean  = d_boxv + PRE;             // PRE dense cluster means
    float4* d_sum   = d_mean + PRE;             // PRE dense weighted sums
    float*  d_area  = (float*)(d_sum + PRE);    // PRE dense mean areas
    float*  d_a1    = d_area + PRE;             // PRE dense det areas
    float*  d_ss    = d_a1 + PRE;               // PRE dense score sums
    float*  d_scr   = d_ss + PRE;               // PRE dense det scores
    int*    d_cnt   = (int*)(d_scr + PRE);      // PRE dense det counts
    int*    d_det   = d_cnt + PRE;              // PRE pos -> det id
    int*    s_pos   = d_det + PRE;              // PRE det id -> pos
    int*    s_nent  = s_pos + PRE;              // PRE entry counts (det-idx)
    int*    s_ent   = s_nent + PRE;             // PRE*SLOTS creator det ids
    unsigned char* s_merged = (unsigned char*)(s_ent + PRE * SLOTS); // PRE

    __shared__ int s_off[NC + 1];
    __shared__ unsigned s_cmask[NWORD];

    const int tid  = threadIdx.x;
    const int wrp  = tid >> 5;
    const int lane = tid & 31;

    // ---- stable class bucketing (warp 0) ----
    if (wrp == 0) {
        int cnt[NC];
        #pragma unroll
        for (int c = 0; c < NC; c++) cnt[c] = 0;
        for (int g = 0; g < PRE; g += 32) {
            const int i = g + lane;
            const int ci = (i < PRE) ? (int)x[i * 6 + 5] : -1;
            #pragma unroll
            for (int c = 0; c < NC; c++)
                cnt[c] += __popc(__ballot_sync(FULL, ci == c));
        }
        int off[NC];
        off[0] = 0;
        #pragma unroll
        for (int c = 1; c < NC; c++) off[c] = off[c - 1] + cnt[c - 1];
        if (lane == 0) {
            s_off[0] = 0;
            #pragma unroll
            for (int c = 0; c < NC; c++) s_off[c + 1] = off[c] + cnt[c];
        }
        int run[NC];
        #pragma unroll
        for (int c = 0; c < NC; c++) run[c] = 0;
        for (int g = 0; g < PRE; g += 32) {
            const int i = g + lane;
            const int ci = (i < PRE) ? (int)x[i * 6 + 5] : -1;
            #pragma unroll
            for (int c = 0; c < NC; c++) {
                const unsigned m = __ballot_sync(FULL, ci == c);
                if (ci == c)
                    d_det[off[c] + run[c] + __popc(m & ((1u << lane) - 1u))] = i;
                run[c] += __popc(m);
            }
        }
    }
    if (tid < NWORD) s_cmask[tid] = 0;
    __syncthreads();

    // ---- dense init: singleton clusters (reference-exact) ----
    for (int k = tid; k < PRE; k += T) {
        const int i = d_det[k];
        const float* d = x + i * 6;
        const float b0 = d[0], b1 = d[1], b2 = d[2], b3 = d[3], s = d[4];
        d_boxv[k] = make_float4(b0, b1, b2, b3);
        d_a1[k]   = __fmul_rn(__fsub_rn(b2, b0), __fsub_rn(b3, b1));
        d_scr[k]  = s;
        float4 sw;
        sw.x = __fmul_rn(s, b0); sw.y = __fmul_rn(s, b1);
        sw.z = __fmul_rn(s, b2); sw.w = __fmul_rn(s, b3);
        d_sum[k] = sw; d_ss[k] = s; d_cnt[k] = 1;
        float4 m;
        m.x = __fdiv_rn(sw.x, s); m.y = __fdiv_rn(sw.y, s);
        m.z = __fdiv_rn(sw.z, s); m.w = __fdiv_rn(sw.w, s);
        d_mean[k] = m;
        d_area[k] = __fmul_rn(__fsub_rn(m.z, m.x), __fsub_rn(m.w, m.y));
        s_pos[i] = k;
        s_merged[i] = 0;
    }
    __syncthreads();

    // ---- phase 1: all same-class pairs, dense sequential, pipelined ----
    for (int c = 0; c < NC; c++) {
        const int off = s_off[c], n = s_off[c + 1] - off;
        const int ntile = (n + 31) >> 5;
        for (int tile = wrp; tile < ntile; tile += (T / 32)) {
            const int bi = tile * 32 + lane;
            const bool act = bi < n;
            float4 bb = make_float4(0.f, 0.f, 0.f, 0.f);
            float a1 = 0.f; int bdet = 0;
            if (act) {
                bb = d_boxv[off + bi];
                a1 = d_a1[off + bi];
                bdet = d_det[off + bi];
            }
            int ne = 0;
            const int hi = min(n, tile * 32 + 32);
            #pragma unroll 4
            for (int ai = 0; ai < hi; ai++) {
                const float4 mm = d_mean[off + ai];   // broadcast LDS
                const float  a2 = d_area[off + ai];   // broadcast LDS
                if (act && ai < bi &&
                    iou_match(bb.x, bb.y, bb.z, bb.w, a1,
                              mm.x, mm.y, mm.z, mm.w, a2)) {
                    if (ne < SLOTS) s_ent[bdet * SLOTS + ne] = d_det[off + ai];
                    ne++;
                }
            }
            if (act) s_nent[bdet] = (ne > SLOTS) ? OVF : ne;
        }
    }
    __syncthreads();

    // candidate bitmask
    for (int i = tid; i < PRE; i += T)
        if (s_nent[i] > 0) atomicOr(&s_cmask[i >> 5], 1u << (i & 31));
    __syncthreads();

    // ---- phase 2: single warp, barrier-free epochs ----
    if (wrp == 0) {
        int cur = 0;
        while (true) {
            // selection: earliest candidate with an alive match
            int t1 = -1, csmin = INT_MAX;
            while (true) {
                int best = INT_MAX;
                const int cw = cur >> 5;
                #pragma unroll
                for (int rep = 0; rep < 2; rep++) {
                    const int w = lane + rep * 32;
                    if (w < NWORD && w >= cw) {
                        unsigned m = s_cmask[w];
                        if (w == cw) m &= ~((1u << (cur & 31)) - 1u);
                        if (m) best = min(best, w * 32 + __ffs(m) - 1);
                    }
                }
                best = __reduce_min_sync(FULL, best);
                if (best == INT_MAX) break;
                const int t = best;
                const int ne = s_nent[t];
                int cs = INT_MAX;
                if (ne == OVF) {
                    // parallel full rescan vs CURRENT means (rare)
                    const int pt = s_pos[t];
                    int c = 0;
                    while (c + 1 < NC && s_off[c + 1] <= pt) c++;
                    const float4 bb = d_boxv[pt];
                    const float a1 = d_a1[pt];
                    int mp = INT_MAX;
                    for (int k = s_off[c] + lane; k < pt; k += 32) {
                        const int a = d_det[k];
                        if (!s_merged[a]) {
                            const float4 mm = d_mean[k];
                            if (iou_match(bb.x, bb.y, bb.z, bb.w, a1,
                                          mm.x, mm.y, mm.z, mm.w, d_area[k]))
                                mp = min(mp, k);
                        }
                    }
                    mp = __reduce_min_sync(FULL, mp);
                    if (mp != INT_MAX) cs = d_det[mp];
                } else {
                    if (lane < ne) {
                        const int a = s_ent[t * SLOTS + lane];
                        if (!s_merged[a]) cs = a;
                    }
                    cs = __reduce_min_sync(FULL, cs);
                }
                if (cs != INT_MAX) { t1 = t; csmin = cs; break; }
                if (lane == 0) s_cmask[t >> 5] &= ~(1u << (t & 31));
                __syncwarp();
                cur = t + 1;   // no alive match -> det t appends (already is)
            }
            if (t1 < 0) break;

            // merge t1 -> cluster csmin (lane 0), broadcast new mean
            int p = 0;
            float nmx = 0.f, nmy = 0.f, nmz = 0.f, nmw = 0.f, na2 = 0.f;
            if (lane == 0) {
                p = s_pos[csmin];
                const int pt = s_pos[t1];
                const float4 b = d_boxv[pt];
                const float s = d_scr[pt];
                float4 sw = d_sum[p];
                float  ss = d_ss[p];
                sw.x = __fadd_rn(sw.x, __fmul_rn(s, b.x));
                sw.y = __fadd_rn(sw.y, __fmul_rn(s, b.y));
                sw.z = __fadd_rn(sw.z, __fmul_rn(s, b.z));
                sw.w = __fadd_rn(sw.w, __fmul_rn(s, b.w));
                ss = __fadd_rn(ss, s);
                d_sum[p] = sw; d_ss[p] = ss; d_cnt[p] += 1;
                nmx = __fdiv_rn(sw.x, ss); nmy = __fdiv_rn(sw.y, ss);
                nmz = __fdiv_rn(sw.z, ss); nmw = __fdiv_rn(sw.w, ss);
                d_mean[p] = make_float4(nmx, nmy, nmz, nmw);
                na2 = __fmul_rn(__fsub_rn(nmz, nmx), __fsub_rn(nmw, nmy));
                d_area[p] = na2;
                s_merged[t1] = 1;
                s_cmask[t1 >> 5] &= ~(1u << (t1 & 31));
            }
            p   = __shfl_sync(FULL, p, 0);
            nmx = __shfl_sync(FULL, nmx, 0);
            nmy = __shfl_sync(FULL, nmy, 0);
            nmz = __shfl_sync(FULL, nmz, 0);
            nmw = __shfl_sync(FULL, nmw, 0);
            na2 = __shfl_sync(FULL, na2, 0);
            __syncwarp();

            // repair: later same-class dets vs csmin's new mean
            int c = 0;
            while (c + 1 < NC && s_off[c + 1] <= p) c++;
            const int hiC = s_off[c + 1];
            for (int k = s_off[c] + lane; k < hiC; k += 32) {
                const int t = d_det[k];
                if (t <= t1) continue;
                const int ne = s_nent[t];
                if (ne == OVF) continue;     // ovf dets always rescan fully
                const float4 bb = d_boxv[k];
                const float a1 = d_a1[k];
                const bool match = iou_match(bb.x, bb.y, bb.z, bb.w, a1,
                                             nmx, nmy, nmz, nmw, na2);
                int fe = -1;
                for (int e = 0; e < ne; e++)
                    if (s_ent[t * SLOTS + e] == csmin) { fe = e; break; }
                if (match && fe < 0) {
                    if (ne < SLOTS) {
                        s_ent[t * SLOTS + ne] = csmin;
                        s_nent[t] = ne + 1;
                    } else s_nent[t] = OVF;
                    atomicOr(&s_cmask[t >> 5], 1u << (t & 31));
                } else if (!match && fe >= 0) {
                    s_ent[t * SLOTS + fe] = s_ent[t * SLOTS + ne - 1];
                    s_nent[t] = ne - 1;
                }
            }
            __syncwarp();
            cur = t1 + 1;
        }
    }
    __syncthreads();

    // ---- export (det-indexed keys; alive order == reference order) ----
    for (int k = tid; k < PRE; k += T) {
        const int i = d_det[k];
        if (!s_merged[i]) {
            int c = 0;
            while (c + 1 < NC && s_off[c + 1] <= k) c++;
            const float4 m = d_mean[k];
            g_box[i * 4 + 0] = m.x;
            g_box[i * 4 + 1] = m.y;
            g_box[i * 4 + 2] = m.z;
            g_box[i * 4 + 3] = m.w;
            const float scv = __fdiv_rn(d_ss[k], fmaxf((float)d_cnt[k], 1.0f));
            g_score[i] = scv;
            g_cls[i]   = (float)c;
            g_key[i]   = scv;          // valid keys >= 0.05
        } else {
            g_key[i] = -1.0f;          // invalid sentinel (matches reference)
        }
        g_rank[i] = 0;
    }
}

// ---------------------------------------------------------------------------
// Kernel 2: partial stable-descending ranks (8 j-blocks x 8 i-chunks)
// ---------------------------------------------------------------------------
__global__ void wbf_rank_part() {
    __shared__ float kk[ICH];
    const int i0 = blockIdx.y * ICH;
    for (int i = threadIdx.x; i < ICH; i += blockDim.x) kk[i] = g_key[i0 + i];
    __syncthreads();

    const int j = blockIdx.x * blockDim.x + threadIdx.x;
    if (j >= PRE) return;
    const float kj = g_key[j];
    int r = 0;
    #pragma unroll 10
    for (int ii = 0; ii < ICH; ii++) {
        const float ki = kk[ii];
        const int i = i0 + ii;
        r += (ki > kj) || (ki == kj && i < j);
    }
    if (r) atomicAdd(&g_rank[j], r);
}

// ---------------------------------------------------------------------------
// Kernel 3: scatter (ranks are a permutation -> each row written once)
// ---------------------------------------------------------------------------
__global__ void wbf_scatter(float* __restrict__ out) {
    const int j = blockIdx.x * blockDim.x + threadIdx.x;
    if (j >= PRE) return;
    const int r = g_rank[j];
    if (r < POST) {
        float* row = out + r * 6;
        if (g_key[j] >= 0.0f) {
            row[0] = g_box[j * 4 + 0];
            row[1] = g_box[j * 4 + 1];
            row[2] = g_box[j * 4 + 2];
            row[3] = g_box[j * 4 + 3];
            row[4] = g_score[j];
            row[5] = g_cls[j];
        } else {
            row[0] = 0.f; row[1] = 0.f; row[2] = 0.f;
            row[3] = 0.f; row[4] = 0.f; row[5] = 0.f;
        }
    }
}

// ---------------------------------------------------------------------------

static const int SCAN_SMEM_BYTES =
    PRE * (int)sizeof(float4) * 3 +       // d_boxv + d_mean + d_sum
    PRE * (int)sizeof(float) * 4 +        // d_area + d_a1 + d_ss + d_scr
    PRE * (int)sizeof(int) * 4 +          // d_cnt + d_det + s_pos + s_nent
    PRE * SLOTS * (int)sizeof(int) +      // s_ent
    PRE;                                  // s_merged

extern "C" void kernel_launch(void* const* d_in, const int* in_sizes, int n_in,
                              void* d_out, int out_size) {
    const float* x = (const float*)d_in[0];
    float* out = (float*)d_out;

    cudaFuncSetAttribute(wbf_scan,
                         cudaFuncAttributeMaxDynamicSharedMemorySize,
                         SCAN_SMEM_BYTES);

    wbf_scan<<<1, T, SCAN_SMEM_BYTES>>>(x);
    wbf_rank_part<<<dim3(8, 8), 256>>>();
    wbf_scatter<<<8, 256>>>(out);
}

// round 9
// speedup vs baseline: 1.2169x; 1.2169x over previous
#include <cuda_runtime.h>
#include <limits.h>

#define PRE 2000
#define POST 300
#define IOU_T 0.55f
#define T 512
#define NC 5
#define SLOTS 4
#define OVF (SLOTS + 1)
#define NWC 16          // per-class candidate-mask words (supports n<=512)
#define ICH 250
#define FULL 0xffffffffu

// Inter-kernel scratch (device globals: allocation-free per harness rules)
__device__ float g_box[PRE * 4];
__device__ float g_score[PRE];
__device__ float g_cls[PRE];
__device__ float g_key[PRE];
__device__ int   g_rank[PRE];

// Exact reference IoU decision: det box (b*, a1) vs cluster mean (m*, a2).
__device__ __forceinline__ bool iou_match(
    float bx1, float by1, float bx2, float by2, float a1,
    float mx, float my, float mz, float mw, float a2)
{
    const float lx = fmaxf(bx1, mx);
    const float ly = fmaxf(by1, my);
    const float rx = fminf(bx2, mz);
    const float ry = fminf(by2, mw);
    const float w  = fmaxf(__fsub_rn(rx, lx), 0.0f);
    const float h  = fmaxf(__fsub_rn(ry, ly), 0.0f);
    const float inter = __fmul_rn(w, h);
    if (inter <= 0.0f) return false;
    const float uni = __fsub_rn(__fadd_rn(a1, a2), inter);  // >= inter > 0
    return __fdiv_rn(inter, uni) > IOU_T;
}

// ---------------------------------------------------------------------------
// Kernel 1: epoch-based WBF, per-class parallel phase 2.
// Classes are fully independent (matching, aliveness, first-match are all
// intra-class; export order is det-indexed). Warp c runs class c's epoch
// loop barrier-free; 5 loops proceed concurrently on 5 warps.
// ---------------------------------------------------------------------------
__global__ void __launch_bounds__(T, 1)
wbf_scan(const float* __restrict__ x) {
    extern __shared__ float smem[];
    float4* d_boxv  = (float4*)smem;            // PRE dense raw det boxes
    float4* d_mean  = d_boxv + PRE;             // PRE dense cluster means
    float4* d_sum   = d_mean + PRE;             // PRE dense weighted sums
    float*  d_area  = (float*)(d_sum + PRE);    // PRE dense mean areas
    float*  d_a1    = d_area + PRE;             // PRE dense det areas
    float*  d_ss    = d_a1 + PRE;               // PRE dense score sums
    float*  d_scr   = d_ss + PRE;               // PRE dense det scores
    int*    d_cnt   = (int*)(d_scr + PRE);      // PRE dense det counts
    int*    d_det   = d_cnt + PRE;              // PRE pos -> det id
    int*    s_nent  = d_det + PRE;              // PRE entry counts (det-idx)
    int*    s_ent   = s_nent + PRE;             // PRE*SLOTS creator det ids
    unsigned char* s_merged = (unsigned char*)(s_ent + PRE * SLOTS); // PRE

    __shared__ int s_off[NC + 1];
    __shared__ unsigned s_cmask[NC][NWC];

    const int tid  = threadIdx.x;
    const int wrp  = tid >> 5;
    const int lane = tid & 31;

    // ---- stable class bucketing (warp 0) ----
    if (wrp == 0) {
        int cnt[NC];
        #pragma unroll
        for (int c = 0; c < NC; c++) cnt[c] = 0;
        for (int g = 0; g < PRE; g += 32) {
            const int i = g + lane;
            const int ci = (i < PRE) ? (int)x[i * 6 + 5] : -1;
            #pragma unroll
            for (int c = 0; c < NC; c++)
                cnt[c] += __popc(__ballot_sync(FULL, ci == c));
        }
        int off[NC];
        off[0] = 0;
        #pragma unroll
        for (int c = 1; c < NC; c++) off[c] = off[c - 1] + cnt[c - 1];
        if (lane == 0) {
            s_off[0] = 0;
            #pragma unroll
            for (int c = 0; c < NC; c++) s_off[c + 1] = off[c] + cnt[c];
        }
        int run[NC];
        #pragma unroll
        for (int c = 0; c < NC; c++) run[c] = 0;
        for (int g = 0; g < PRE; g += 32) {
            const int i = g + lane;
            const int ci = (i < PRE) ? (int)x[i * 6 + 5] : -1;
            #pragma unroll
            for (int c = 0; c < NC; c++) {
                const unsigned m = __ballot_sync(FULL, ci == c);
                if (ci == c)
                    d_det[off[c] + run[c] + __popc(m & ((1u << lane) - 1u))] = i;
                run[c] += __popc(m);
            }
        }
    }
    if (tid < NC * NWC) ((unsigned*)s_cmask)[tid] = 0;
    __syncthreads();

    // ---- dense init: singleton clusters (reference-exact) ----
    for (int k = tid; k < PRE; k += T) {
        const int i = d_det[k];
        const float* d = x + i * 6;
        const float b0 = d[0], b1 = d[1], b2 = d[2], b3 = d[3], s = d[4];
        d_boxv[k] = make_float4(b0, b1, b2, b3);
        d_a1[k]   = __fmul_rn(__fsub_rn(b2, b0), __fsub_rn(b3, b1));
        d_scr[k]  = s;
        float4 sw;
        sw.x = __fmul_rn(s, b0); sw.y = __fmul_rn(s, b1);
        sw.z = __fmul_rn(s, b2); sw.w = __fmul_rn(s, b3);
        d_sum[k] = sw; d_ss[k] = s; d_cnt[k] = 1;
        float4 m;
        m.x = __fdiv_rn(sw.x, s); m.y = __fdiv_rn(sw.y, s);
        m.z = __fdiv_rn(sw.z, s); m.w = __fdiv_rn(sw.w, s);
        d_mean[k] = m;
        d_area[k] = __fmul_rn(__fsub_rn(m.z, m.x), __fsub_rn(m.w, m.y));
        s_merged[i] = 0;
    }
    __syncthreads();

    // ---- phase 1: all same-class pairs, dense sequential, pipelined ----
    for (int c = 0; c < NC; c++) {
        const int off = s_off[c], n = s_off[c + 1] - off;
        const int ntile = (n + 31) >> 5;
        for (int tile = wrp; tile < ntile; tile += (T / 32)) {
            const int bi = tile * 32 + lane;
            const bool act = bi < n;
            float4 bb = make_float4(0.f, 0.f, 0.f, 0.f);
            float a1 = 0.f; int bdet = 0;
            if (act) {
                bb = d_boxv[off + bi];
                a1 = d_a1[off + bi];
                bdet = d_det[off + bi];
            }
            int ne = 0;
            const int hi = min(n, tile * 32 + 32);
            #pragma unroll 4
            for (int ai = 0; ai < hi; ai++) {
                const float4 mm = d_mean[off + ai];   // broadcast LDS
                const float  a2 = d_area[off + ai];   // broadcast LDS
                if (act && ai < bi &&
                    iou_match(bb.x, bb.y, bb.z, bb.w, a1,
                              mm.x, mm.y, mm.z, mm.w, a2)) {
                    if (ne < SLOTS) s_ent[bdet * SLOTS + ne] = d_det[off + ai];
                    ne++;
                }
            }
            if (act) {
                s_nent[bdet] = (ne > SLOTS) ? OVF : ne;
                if (ne > 0)
                    atomicOr(&s_cmask[c][bi >> 5], 1u << (bi & 31));
            }
        }
    }
    __syncthreads();

    // ---- phase 2: 5 concurrent per-class epoch loops (warps 0..4) ----
    if (wrp < NC) {
        const int c = wrp;
        const int off = s_off[c];
        const int n = s_off[c + 1] - off;
        const int nw = (n + 31) >> 5;
        unsigned* mask = s_cmask[c];
        int curb = 0;   // dense bit cursor within class

        while (true) {
            // -- selection: first candidate bit >= curb with alive match --
            int selb = -1, csmin = INT_MAX;
            while (true) {
                const int w0 = curb >> 5;
                int best = INT_MAX;
                if (lane < nw && lane >= w0) {
                    unsigned m = mask[lane];
                    if (lane == w0) m &= ~((1u << (curb & 31)) - 1u);
                    if (m) best = lane * 32 + __ffs(m) - 1;
                }
                best = __reduce_min_sync(FULL, best);
                if (best == INT_MAX) break;
                const int tpos = off + best;
                const int tdet = d_det[tpos];
                const int ne = s_nent[tdet];
                int cs = INT_MAX;
                if (ne == OVF) {
                    // parallel rescan vs CURRENT means (rare)
                    const float4 bb = d_boxv[tpos];
                    const float a1 = d_a1[tpos];
                    int mp = INT_MAX;
                    for (int k = off + lane; k < tpos; k += 32) {
                        if (!s_merged[d_det[k]]) {
                            const float4 mm = d_mean[k];
                            if (iou_match(bb.x, bb.y, bb.z, bb.w, a1,
                                          mm.x, mm.y, mm.z, mm.w, d_area[k]))
                                mp = min(mp, k);
                        }
                    }
                    mp = __reduce_min_sync(FULL, mp);
                    if (mp != INT_MAX) cs = d_det[mp];
                } else {
                    if (lane < ne) {
                        const int a = s_ent[tdet * SLOTS + lane];
                        if (!s_merged[a]) cs = a;
                    }
                    cs = __reduce_min_sync(FULL, cs);
                }
                if (cs != INT_MAX) { selb = best; csmin = cs; break; }
                if (lane == 0) mask[best >> 5] &= ~(1u << (best & 31));
                __syncwarp();
                curb = best + 1;   // settled: det appends (already singleton)
            }
            if (selb < 0) break;

            // -- merge selected det into cluster csmin (lane 0) --
            const int tpos = off + selb;
            const int t1 = d_det[tpos];
            int p = 0;
            float nmx = 0.f, nmy = 0.f, nmz = 0.f, nmw = 0.f, na2 = 0.f;
            if (lane == 0) {
                // creator position: csmin's dense pos (binary search not
                // needed: positions are det-ordered; find via linear probe
                // from selb downward is O(n) worst -- store pos instead)
                // We keep a det->pos map implicitly: scan is avoided by
                // recording pos in s_ent? Simpler: search within class.
                int lo = off, hi2 = tpos;
                while (lo < hi2) {          // binary search d_det (sorted)
                    const int mid = (lo + hi2) >> 1;
                    if (d_det[mid] < csmin) lo = mid + 1; else hi2 = mid;
                }
                p = lo;
                const float4 b = d_boxv[tpos];
                const float s = d_scr[tpos];
                float4 sw = d_sum[p];
                float  ss = d_ss[p];
                sw.x = __fadd_rn(sw.x, __fmul_rn(s, b.x));
                sw.y = __fadd_rn(sw.y, __fmul_rn(s, b.y));
                sw.z = __fadd_rn(sw.z, __fmul_rn(s, b.z));
                sw.w = __fadd_rn(sw.w, __fmul_rn(s, b.w));
                ss = __fadd_rn(ss, s);
                d_sum[p] = sw; d_ss[p] = ss; d_cnt[p] += 1;
                nmx = __fdiv_rn(sw.x, ss); nmy = __fdiv_rn(sw.y, ss);
                nmz = __fdiv_rn(sw.z, ss); nmw = __fdiv_rn(sw.w, ss);
                d_mean[p] = make_float4(nmx, nmy, nmz, nmw);
                na2 = __fmul_rn(__fsub_rn(nmz, nmx), __fsub_rn(nmw, nmy));
                d_area[p] = na2;
                s_merged[t1] = 1;
                mask[selb >> 5] &= ~(1u << (selb & 31));
            }
            nmx = __shfl_sync(FULL, nmx, 0);
            nmy = __shfl_sync(FULL, nmy, 0);
            nmz = __shfl_sync(FULL, nmz, 0);
            nmw = __shfl_sync(FULL, nmw, 0);
            na2 = __shfl_sync(FULL, na2, 0);
            __syncwarp();

            // -- repair: dets after t1 in this class vs csmin's new mean --
            for (int k = tpos + 1 + lane; k < off + n; k += 32) {
                const int t = d_det[k];
                const int ne = s_nent[t];
                if (ne == OVF) continue;     // ovf dets always rescan fully
                const float4 bb = d_boxv[k];
                const float a1 = d_a1[k];
                const bool match = iou_match(bb.x, bb.y, bb.z, bb.w, a1,
                                             nmx, nmy, nmz, nmw, na2);
                int fe = -1;
                for (int e = 0; e < ne; e++)
                    if (s_ent[t * SLOTS + e] == csmin) { fe = e; break; }
                if (match && fe < 0) {
                    if (ne < SLOTS) {
                        s_ent[t * SLOTS + ne] = csmin;
                        s_nent[t] = ne + 1;
                    } else s_nent[t] = OVF;
                    atomicOr(&mask[(k - off) >> 5], 1u << ((k - off) & 31));
                } else if (!match && fe >= 0) {
                    s_ent[t * SLOTS + fe] = s_ent[t * SLOTS + ne - 1];
                    s_nent[t] = ne - 1;
                }
            }
            __syncwarp();
            curb = selb + 1;
        }
    }
    __syncthreads();

    // ---- export (det-indexed keys; alive order == reference order) ----
    for (int k = tid; k < PRE; k += T) {
        const int i = d_det[k];
        if (!s_merged[i]) {
            int c = 0;
            while (c + 1 < NC && s_off[c + 1] <= k) c++;
            const float4 m = d_mean[k];
            g_box[i * 4 + 0] = m.x;
            g_box[i * 4 + 1] = m.y;
            g_box[i * 4 + 2] = m.z;
            g_box[i * 4 + 3] = m.w;
            const float scv = __fdiv_rn(d_ss[k], fmaxf((float)d_cnt[k], 1.0f));
            g_score[i] = scv;
            g_cls[i]   = (float)c;
            g_key[i]   = scv;          // valid keys >= 0.05
        } else {
            g_key[i] = -1.0f;          // invalid sentinel (matches reference)
        }
        g_rank[i] = 0;
    }
}

// ---------------------------------------------------------------------------
// Kernel 2: partial stable-descending ranks (8 j-blocks x 8 i-chunks)
// ---------------------------------------------------------------------------
__global__ void wbf_rank_part() {
    __shared__ float kk[ICH];
    const int i0 = blockIdx.y * ICH;
    for (int i = threadIdx.x; i < ICH; i += blockDim.x) kk[i] = g_key[i0 + i];
    __syncthreads();

    const int j = blockIdx.x * blockDim.x + threadIdx.x;
    if (j >= PRE) return;
    const float kj = g_key[j];
    int r = 0;
    #pragma unroll 10
    for (int ii = 0; ii < ICH; ii++) {
        const float ki = kk[ii];
        const int i = i0 + ii;
        r += (ki > kj) || (ki == kj && i < j);
    }
    if (r) atomicAdd(&g_rank[j], r);
}

// ---------------------------------------------------------------------------
// Kernel 3: scatter (ranks are a permutation -> each row written once)
// ---------------------------------------------------------------------------
__global__ void wbf_scatter(float* __restrict__ out) {
    const int j = blockIdx.x * blockDim.x + threadIdx.x;
    if (j >= PRE) return;
    const int r = g_rank[j];
    if (r < POST) {
        float* row = out + r * 6;
        if (g_key[j] >= 0.0f) {
            row[0] = g_box[j * 4 + 0];
            row[1] = g_box[j * 4 + 1];
            row[2] = g_box[j * 4 + 2];
            row[3] = g_box[j * 4 + 3];
            row[4] = g_score[j];
            row[5] = g_cls[j];
        } else {
            row[0] = 0.f; row[1] = 0.f; row[2] = 0.f;
            row[3] = 0.f; row[4] = 0.f; row[5] = 0.f;
        }
    }
}

// ---------------------------------------------------------------------------

static const int SCAN_SMEM_BYTES =
    PRE * (int)sizeof(float4) * 3 +       // d_boxv + d_mean + d_sum
    PRE * (int)sizeof(float) * 4 +        // d_area + d_a1 + d_ss + d_scr
    PRE * (int)sizeof(int) * 3 +          // d_cnt + d_det + s_nent
    PRE * SLOTS * (int)sizeof(int) +      // s_ent
    PRE;                                  // s_merged

extern "C" void kernel_launch(void* const* d_in, const int* in_sizes, int n_in,
                              void* d_out, int out_size) {
    const float* x = (const float*)d_in[0];
    float* out = (float*)d_out;

    cudaFuncSetAttribute(wbf_scan,
                         cudaFuncAttributeMaxDynamicSharedMemorySize,
                         SCAN_SMEM_BYTES);

    wbf_scan<<<1, T, SCAN_SMEM_BYTES>>>(x);
    wbf_rank_part<<<dim3(8, 8), 256>>>();
    wbf_scatter<<<8, 256>>>(out);
}

// round 11
// speedup vs baseline: 1.3189x; 1.0838x over previous
#include <cuda_runtime.h>
#include <limits.h>

#define PRE 2000
#define POST 300
#define IOU_T 0.55f
#define T 512
#define NWP 16         // warps per block
#define CHUNK 125      // dets per warp for bucketing (16*125 = 2000)
#define NC 5
#define SLOTS 4
#define OVF 5          // sentinel for overflowed entry list
#define MAXP 512       // max merge pairs
#define MAXM 16        // max merges per cluster
#define MAXU 64        // max flagged clusters per class
#define ICH 250
#define FULL 0xffffffffu

// Inter-kernel scratch (device globals: allocation-free per harness rules)
__device__ float g_box[PRE * 4];
__device__ float g_score[PRE];
__device__ float g_cls[PRE];
__device__ float g_key[PRE];
__device__ int   g_rank[PRE];

// Exact reference IoU decision: det box (b*, a1) vs cluster mean (m*, a2).
__device__ __forceinline__ bool iou_match(
    float bx1, float by1, float bx2, float by2, float a1,
    float mx, float my, float mz, float mw, float a2)
{
    const float lx = fmaxf(bx1, mx);
    const float ly = fmaxf(by1, my);
    const float rx = fminf(bx2, mz);
    const float ry = fminf(by2, mw);
    const float w  = fmaxf(__fsub_rn(rx, lx), 0.0f);
    const float h  = fmaxf(__fsub_rn(ry, ly), 0.0f);
    const float inter = __fmul_rn(w, h);
    if (inter <= 0.0f) return false;
    const float uni = __fsub_rn(__fadd_rn(a1, a2), inter);  // >= inter > 0
    return __fdiv_rn(inter, uni) > IOU_T;
}

// ---------------------------------------------------------------------------
// Kernel 1: batched resolve+validate WBF.
// Phase 1: per-det match lists vs singleton means (exact until a merge).
// Resolve: parallel dataflow fixpoint over det order (det merges iff it has
//   an alive matching creator; creator alive iff it didn't merge itself).
// Validate: for every merged-into cluster, recheck later same-class dets vs
//   the time-correct prefix means; flips -> patch lists, re-resolve.
// Converges in ~1-2 outer iterations (flips ~0 in practice).
// ---------------------------------------------------------------------------
__global__ void __launch_bounds__(T, 1)
wbf_scan(const float* __restrict__ x) {
    extern __shared__ float smem[];
    float4* d_boxv = (float4*)smem;             // PRE dense raw det boxes
    float4* d_mean = d_boxv + PRE;              // PRE dense cluster means
    float*  d_area = (float*)(d_mean + PRE);    // PRE dense mean areas
    float*  d_a1   = d_area + PRE;              // PRE dense det areas
    float*  d_ss   = d_a1 + PRE;                // PRE dense score sums
    float*  d_scr  = d_ss + PRE;                // PRE dense det scores
    int*    d_cnt  = (int*)(d_scr + PRE);       // PRE dense det counts
    int*    d_det  = d_cnt + PRE;               // PRE pos -> det id
    int*    s_pos  = d_det + PRE;               // PRE det id -> pos
    int*    s_nent = s_pos + PRE;               // PRE entry counts
    int*    s_stat = s_nent + PRE;              // PRE 0=unk 1=alive 2=merged
    int*    s_tgt  = s_stat + PRE;              // PRE merge target
    int*    s_ent  = s_tgt + PRE;               // PRE*SLOTS creators (asc)

    __shared__ int s_off[NC + 1];
    __shared__ int s_wcnt[NWP][NC], s_wbase[NWP][NC];
    __shared__ int m_t[MAXP], m_tgt[MAXP];
    __shared__ int s_uniq[NC][MAXU];
    __shared__ int s_mm[NC][MAXM];
    __shared__ int s_np, s_changed, s_dirty;

    const int tid  = threadIdx.x;
    const int wrp  = tid >> 5;
    const int lane = tid & 31;
    const unsigned lt = (1u << lane) - 1u;

    // ---- parallel stable class bucketing (16 warps, chunked) ----
    {
        const int beg = wrp * CHUNK, end = beg + CHUNK;
        int cnt[NC];
        #pragma unroll
        for (int c = 0; c < NC; c++) cnt[c] = 0;
        for (int g = beg; g < end; g += 32) {
            const int i = g + lane;
            const int ci = (i < end) ? (int)x[i * 6 + 5] : -1;
            #pragma unroll
            for (int c = 0; c < NC; c++)
                cnt[c] += __popc(__ballot_sync(FULL, ci == c));
        }
        if (lane == 0)
            #pragma unroll
            for (int c = 0; c < NC; c++) s_wcnt[wrp][c] = cnt[c];
        __syncthreads();
        if (tid == 0) {
            int off = 0;
            for (int c = 0; c < NC; c++) {
                s_off[c] = off;
                int run = 0;
                for (int w = 0; w < NWP; w++) {
                    s_wbase[w][c] = off + run;
                    run += s_wcnt[w][c];
                }
                off += run;
            }
            s_off[NC] = off;   // == PRE
        }
        __syncthreads();
        int run[NC];
        #pragma unroll
        for (int c = 0; c < NC; c++) run[c] = 0;
        for (int g = beg; g < end; g += 32) {
            const int i = g + lane;
            const int ci = (i < end) ? (int)x[i * 6 + 5] : -1;
            #pragma unroll
            for (int c = 0; c < NC; c++) {
                const unsigned b = __ballot_sync(FULL, ci == c);
                if (ci == c)
                    d_det[s_wbase[wrp][c] + run[c] + __popc(b & lt)] = i;
                run[c] += __popc(b);
            }
        }
    }
    __syncthreads();

    // ---- dense init: singleton clusters (reference-exact) ----
    for (int k = tid; k < PRE; k += T) {
        const int i = d_det[k];
        const float* d = x + i * 6;
        const float b0 = d[0], b1 = d[1], b2 = d[2], b3 = d[3], s = d[4];
        d_boxv[k] = make_float4(b0, b1, b2, b3);
        d_a1[k]   = __fmul_rn(__fsub_rn(b2, b0), __fsub_rn(b3, b1));
        d_scr[k]  = s;
        d_ss[k] = s; d_cnt[k] = 1;
        float4 m;
        m.x = __fdiv_rn(__fmul_rn(s, b0), s);
        m.y = __fdiv_rn(__fmul_rn(s, b1), s);
        m.z = __fdiv_rn(__fmul_rn(s, b2), s);
        m.w = __fdiv_rn(__fmul_rn(s, b3), s);
        d_mean[k] = m;
        d_area[k] = __fmul_rn(__fsub_rn(m.z, m.x), __fsub_rn(m.w, m.y));
        s_pos[i] = k;
    }
    __syncthreads();

    // ---- phase 1: all same-class pairs vs singleton means ----
    for (int c = 0; c < NC; c++) {
        const int off = s_off[c], n = s_off[c + 1] - off;
        const int ntile = (n + 31) >> 5;
        for (int tile = wrp; tile < ntile; tile += NWP) {
            const int bi = tile * 32 + lane;
            const bool act = bi < n;
            float4 bb = make_float4(0.f, 0.f, 0.f, 0.f);
            float a1 = 0.f; int bdet = 0;
            if (act) {
                bb = d_boxv[off + bi];
                a1 = d_a1[off + bi];
                bdet = d_det[off + bi];
            }
            int ne = 0;
            const int hi = min(n, tile * 32 + 32);
            #pragma unroll 4
            for (int ai = 0; ai < hi; ai++) {
                const float4 mm = d_mean[off + ai];   // broadcast LDS
                const float  a2 = d_area[off + ai];
                if (act && ai < bi &&
                    iou_match(bb.x, bb.y, bb.z, bb.w, a1,
                              mm.x, mm.y, mm.z, mm.w, a2)) {
                    if (ne < SLOTS) s_ent[bdet * SLOTS + ne] = d_det[off + ai];
                    ne++;                            // ascending creator order
                }
            }
            if (act) {
                s_nent[bdet] = (ne > SLOTS) ? OVF : ne;
                s_stat[bdet] = (ne > 0) ? 0 : 1;
            }
        }
    }
    __syncthreads();

    // ---- outer resolve/validate loop ----
    for (int it = 0; it < 24; it++) {
        // -- resolve fixpoint (rounds <= dependency depth) --
        while (true) {
            if (tid == 0) s_changed = 0;
            __syncthreads();
            for (int i = tid; i < PRE; i += T) {
                if (s_stat[i] != 0) continue;
                const int ne = s_nent[i];
                int res = 1, tgt = -1;
                if (ne == OVF) {
                    // full rescan (probability ~0): vs current means
                    const int p = s_pos[i];
                    int c = 0;
                    while (c + 1 < NC && s_off[c + 1] <= p) c++;
                    const float4 bb = d_boxv[p];
                    const float a1 = d_a1[p];
                    for (int k = s_off[c]; k < p; k++) {
                        const int a = d_det[k];
                        const int st = s_stat[a];
                        if (st == 0) { res = 0; break; }
                        if (st == 1) {
                            const float4 mm = d_mean[k];
                            if (iou_match(bb.x, bb.y, bb.z, bb.w, a1,
                                          mm.x, mm.y, mm.z, mm.w, d_area[k])) {
                                res = 2; tgt = a; break;
                            }
                        }
                    }
                } else {
                    for (int e = 0; e < ne; e++) {
                        const int a = s_ent[i * SLOTS + e];
                        const int st = s_stat[a];
                        if (st == 0) { res = 0; break; }
                        if (st == 1) { res = 2; tgt = a; break; }
                    }
                }
                if (res == 1) { s_stat[i] = 1; s_changed = 1; }
                else if (res == 2) { s_tgt[i] = tgt; s_stat[i] = 2; s_changed = 1; }
            }
            __syncthreads();
            if (!s_changed) break;
        }

        // -- collect merge pairs --
        if (tid == 0) { s_np = 0; s_dirty = 0; }
        __syncthreads();
        for (int i = tid; i < PRE; i += T)
            if (s_stat[i] == 2) {
                const int j = atomicAdd(&s_np, 1);
                if (j < MAXP) { m_t[j] = i; m_tgt[j] = s_tgt[i]; }
            }
        __syncthreads();
        const int np = min(s_np, MAXP);
        if (np == 0) break;   // no merges at all: singleton state is final

        // -- global re-init to singleton state --
        for (int k = tid; k < PRE; k += T) {
            const float4 b = d_boxv[k];
            const float s = d_scr[k];
            d_ss[k] = s; d_cnt[k] = 1;
            float4 m;
            m.x = __fdiv_rn(__fmul_rn(s, b.x), s);
            m.y = __fdiv_rn(__fmul_rn(s, b.y), s);
            m.z = __fdiv_rn(__fmul_rn(s, b.z), s);
            m.w = __fdiv_rn(__fmul_rn(s, b.w), s);
            d_mean[k] = m;
            d_area[k] = __fmul_rn(__fsub_rn(m.z, m.x), __fsub_rn(m.w, m.y));
        }
        __syncthreads();

        // -- per-class build + validate (warp c handles class c) --
        if (wrp < NC) {
            const int c = wrp;
            const int cBeg = s_off[c], cEnd = s_off[c + 1];

            // unique flagged clusters of this class
            int nu = 0;
            for (int j0 = 0; j0 < np; j0 += 32) {
                const int j = j0 + lane;
                bool take = false; int a = -1;
                if (j < np) {
                    a = m_tgt[j];
                    const int pa = s_pos[a];
                    if (pa >= cBeg && pa < cEnd) {
                        take = true;
                        for (int j2 = 0; j2 < j; j2++)
                            if (m_tgt[j2] == a) { take = false; break; }
                    }
                }
                const unsigned b = __ballot_sync(FULL, take);
                if (take) {
                    const int idx = nu + __popc(b & lt);
                    if (idx < MAXU) s_uniq[c][idx] = a;
                }
                nu += __popc(b);
            }
            nu = min(nu, MAXU);

            for (int ui = 0; ui < nu; ui++) {
                const int a = s_uniq[c][ui];
                const int p = s_pos[a];

                // gather this cluster's merges
                int nm = 0;
                for (int j0 = 0; j0 < np; j0 += 32) {
                    const int j = j0 + lane;
                    const bool take = (j < np) && (m_tgt[j] == a);
                    const unsigned b = __ballot_sync(FULL, take);
                    if (take) {
                        const int idx = nm + __popc(b & lt);
                        if (idx < MAXM) s_mm[c][idx] = m_t[j];
                    }
                    nm += __popc(b);
                }
                nm = min(nm, MAXM);
                __syncwarp();

                if (lane == 0) {
                    // sort merges ascending (tiny insertion sort)
                    for (int e = 1; e < nm; e++) {
                        const int v = s_mm[c][e];
                        int f = e - 1;
                        while (f >= 0 && s_mm[c][f] > v) {
                            s_mm[c][f + 1] = s_mm[c][f]; f--;
                        }
                        s_mm[c][f + 1] = v;
                    }
                    // apply merges (reference-exact sequential chain)
                    const float4 b = d_boxv[p];
                    const float s = d_scr[p];
                    float swx = __fmul_rn(s, b.x), swy = __fmul_rn(s, b.y);
                    float swz = __fmul_rn(s, b.z), sww = __fmul_rn(s, b.w);
                    float ss = s; int cn = 1;
                    for (int e = 0; e < nm; e++) {
                        const int pm = s_pos[s_mm[c][e]];
                        const float4 bm = d_boxv[pm];
                        const float sm = d_scr[pm];
                        swx = __fadd_rn(swx, __fmul_rn(sm, bm.x));
                        swy = __fadd_rn(swy, __fmul_rn(sm, bm.y));
                        swz = __fadd_rn(swz, __fmul_rn(sm, bm.z));
                        sww = __fadd_rn(sww, __fmul_rn(sm, bm.w));
                        ss = __fadd_rn(ss, sm); cn++;
                    }
                    float4 m;
                    m.x = __fdiv_rn(swx, ss); m.y = __fdiv_rn(swy, ss);
                    m.z = __fdiv_rn(swz, ss); m.w = __fdiv_rn(sww, ss);
                    d_mean[p] = m; d_ss[p] = ss; d_cnt[p] = cn;
                    d_area[p] = __fmul_rn(__fsub_rn(m.z, m.x),
                                          __fsub_rn(m.w, m.y));
                }
                __syncwarp();

                // validate later same-class dets vs time-correct prefixes.
                // dets before the first merge saw the singleton state (= phase
                // 1 / previous lists): no flip possible; start after it.
                const int kStart = s_pos[s_mm[c][0]] + 1;
                const float4 ab = d_boxv[p];
                const float as = d_scr[p];
                for (int k = kStart + lane; k < cEnd; k += 32) {
                    const int tu = d_det[k];
                    const int ne = s_nent[tu];
                    if (ne == OVF) continue;        // ovf dets rescan anyway
                    // prefix state: singleton + merges with det id < tu
                    float swx = __fmul_rn(as, ab.x), swy = __fmul_rn(as, ab.y);
                    float swz = __fmul_rn(as, ab.z), sww = __fmul_rn(as, ab.w);
                    float ss = as;
                    for (int e = 0; e < nm; e++) {
                        const int mdet = s_mm[c][e];
                        if (mdet >= tu) break;
                        const int pm = s_pos[mdet];
                        const float4 bm = d_boxv[pm];
                        const float sm = d_scr[pm];
                        swx = __fadd_rn(swx, __fmul_rn(sm, bm.x));
                        swy = __fadd_rn(swy, __fmul_rn(sm, bm.y));
                        swz = __fadd_rn(swz, __fmul_rn(sm, bm.z));
                        sww = __fadd_rn(sww, __fmul_rn(sm, bm.w));
                        ss = __fadd_rn(ss, sm);
                    }
                    const float mx = __fdiv_rn(swx, ss);
                    const float my = __fdiv_rn(swy, ss);
                    const float mz = __fdiv_rn(swz, ss);
                    const float mw = __fdiv_rn(sww, ss);
                    const float a2 = __fmul_rn(__fsub_rn(mz, mx),
                                               __fsub_rn(mw, my));
                    const float4 ub = d_boxv[k];
                    const bool match = iou_match(ub.x, ub.y, ub.z, ub.w,
                                                 d_a1[k], mx, my, mz, mw, a2);
                    int fe = -1;
                    for (int e = 0; e < ne; e++)
                        if (s_ent[tu * SLOTS + e] == a) { fe = e; break; }
                    if (match && fe < 0) {
                        if (ne < SLOTS) {
                            int ip = ne;
                            for (int e = 0; e < ne; e++)
                                if (s_ent[tu * SLOTS + e] > a) { ip = e; break; }
                            for (int e = ne; e > ip; e--)
                                s_ent[tu * SLOTS + e] = s_ent[tu * SLOTS + e - 1];
                            s_ent[tu * SLOTS + ip] = a;
                            s_nent[tu] = ne + 1;
                        } else s_nent[tu] = OVF;
                        s_dirty = 1;
                    } else if (!match && fe >= 0) {
                        for (int e = fe; e < ne - 1; e++)
                            s_ent[tu * SLOTS + e] = s_ent[tu * SLOTS + e + 1];
                        s_nent[tu] = ne - 1;
                        s_dirty = 1;
                    }
                }
                __syncwarp();
            }
        }
        __syncthreads();
        if (!s_dirty) break;

        // lists changed: reset statuses and re-resolve
        for (int i = tid; i < PRE; i += T)
            s_stat[i] = (s_nent[i] > 0) ? 0 : 1;
        __syncthreads();
    }
    __syncthreads();

    // ---- export (det-indexed keys; alive order == reference order) ----
    for (int k = tid; k < PRE; k += T) {
        const int i = d_det[k];
        if (s_stat[i] != 2) {
            int c = 0;
            while (c + 1 < NC && s_off[c + 1] <= k) c++;
            const float4 m = d_mean[k];
            g_box[i * 4 + 0] = m.x;
            g_box[i * 4 + 1] = m.y;
            g_box[i * 4 + 2] = m.z;
            g_box[i * 4 + 3] = m.w;
            const float scv = __fdiv_rn(d_ss[k], fmaxf((float)d_cnt[k], 1.0f));
            g_score[i] = scv;
            g_cls[i]   = (float)c;
            g_key[i]   = scv;          // valid keys >= 0.05
        } else {
            g_key[i] = -1.0f;          // invalid sentinel (matches reference)
        }
        g_rank[i] = 0;
    }
}

// ---------------------------------------------------------------------------
// Kernel 2: partial stable-descending ranks (8 j-blocks x 8 i-chunks)
// ---------------------------------------------------------------------------
__global__ void wbf_rank_part() {
    __shared__ float kk[ICH];
    const int i0 = blockIdx.y * ICH;
    for (int i = threadIdx.x; i < ICH; i += blockDim.x) kk[i] = g_key[i0 + i];
    __syncthreads();

    const int j = blockIdx.x * blockDim.x + threadIdx.x;
    if (j >= PRE) return;
    const float kj = g_key[j];
    int r = 0;
    #pragma unroll 10
    for (int ii = 0; ii < ICH; ii++) {
        const float ki = kk[ii];
        const int i = i0 + ii;
        r += (ki > kj) || (ki == kj && i < j);
    }
    if (r) atomicAdd(&g_rank[j], r);
}

// ---------------------------------------------------------------------------
// Kernel 3: scatter (ranks are a permutation -> each row written once)
// ---------------------------------------------------------------------------
__global__ void wbf_scatter(float* __restrict__ out) {
    const int j = blockIdx.x * blockDim.x + threadIdx.x;
    if (j >= PRE) return;
    const int r = g_rank[j];
    if (r < POST) {
        float* row = out + r * 6;
        if (g_key[j] >= 0.0f) {
            row[0] = g_box[j * 4 + 0];
            row[1] = g_box[j * 4 + 1];
            row[2] = g_box[j * 4 + 2];
            row[3] = g_box[j * 4 + 3];
            row[4] = g_score[j];
            row[5] = g_cls[j];
        } else {
            row[0] = 0.f; row[1] = 0.f; row[2] = 0.f;
            row[3] = 0.f; row[4] = 0.f; row[5] = 0.f;
        }
    }
}

// ---------------------------------------------------------------------------

static const int SCAN_SMEM_BYTES =
    PRE * (int)sizeof(float4) * 2 +       // d_boxv + d_mean
    PRE * (int)sizeof(float) * 4 +        // d_area + d_a1 + d_ss + d_scr
    PRE * (int)sizeof(int) * 6 +          // d_cnt d_det s_pos s_nent s_stat s_tgt
    PRE * SLOTS * (int)sizeof(int);       // s_ent

extern "C" void kernel_launch(void* const* d_in, const int* in_sizes, int n_in,
                              void* d_out, int out_size) {
    const float* x = (const float*)d_in[0];
    float* out = (float*)d_out;

    cudaFuncSetAttribute(wbf_scan,
                         cudaFuncAttributeMaxDynamicSharedMemorySize,
                         SCAN_SMEM_BYTES);

    wbf_scan<<<1, T, SCAN_SMEM_BYTES>>>(x);
    wbf_rank_part<<<dim3(8, 8), 256>>>();
    wbf_scatter<<<8, 256>>>(out);
}

// round 12
// speedup vs baseline: 1.8667x; 1.4153x over previous
#include <cuda_runtime.h>
#include <limits.h>
#include <math_constants.h>

#define PRE 2000
#define POST 300
#define IOU_T 0.55f
#define T 512
#define NWP 16         // warps per block
#define CHUNK 125      // dets per warp for bucketing (16*125 = 2000)
#define NC 5
#define SLOTS 4
#define OVF 5          // sentinel for overflowed entry list
#define MAXP 512       // max merge pairs
#define MAXM 24        // max merges per cluster (lanes 1..nm compute prefixes)
#define MAXU 64        // max flagged clusters per class
#define ICH 250
#define FULL 0xffffffffu

// Inter-kernel scratch (device globals: allocation-free per harness rules)
__device__ float g_box[PRE * 4];
__device__ float g_score[PRE];
__device__ float g_cls[PRE];
__device__ float g_key[PRE];
__device__ int   g_rank[PRE];

// Exact reference IoU decision: det box (b*, a1) vs cluster mean (m*, a2).
__device__ __forceinline__ bool iou_match(
    float bx1, float by1, float bx2, float by2, float a1,
    float mx, float my, float mz, float mw, float a2)
{
    const float lx = fmaxf(bx1, mx);
    const float ly = fmaxf(by1, my);
    const float rx = fminf(bx2, mz);
    const float ry = fminf(by2, mw);
    const float w  = fmaxf(__fsub_rn(rx, lx), 0.0f);
    const float h  = fmaxf(__fsub_rn(ry, ly), 0.0f);
    const float inter = __fmul_rn(w, h);
    if (inter <= 0.0f) return false;
    const float uni = __fsub_rn(__fadd_rn(a1, a2), inter);  // >= inter > 0
    return __fdiv_rn(inter, uni) > IOU_T;
}

// ---------------------------------------------------------------------------
// Kernel 1: batched resolve+validate WBF (prefix-state validate, flat phase 1)
// ---------------------------------------------------------------------------
__global__ void __launch_bounds__(T, 1)
wbf_scan(const float* __restrict__ x) {
    extern __shared__ float smem[];
    float4* d_boxv = (float4*)smem;             // PRE dense raw det boxes
    float4* d_mean = d_boxv + PRE;              // PRE dense cluster means
    float*  d_area = (float*)(d_mean + PRE);    // PRE dense mean areas
    float*  d_a1   = d_area + PRE;              // PRE dense det areas
    float*  d_ss   = d_a1 + PRE;                // PRE dense score sums
    float*  d_scr  = d_ss + PRE;                // PRE dense det scores
    int*    d_cnt  = (int*)(d_scr + PRE);       // PRE dense det counts
    int*    d_det  = d_cnt + PRE;               // PRE pos -> det id (asc ids
    int*    s_pos  = d_det + PRE;               //   within each class)
    int*    s_nent = s_pos + PRE;               // PRE entry counts
    int*    s_stat = s_nent + PRE;              // PRE 0=unk 1=alive 2=merged
    int*    s_tgt  = s_stat + PRE;              // PRE merge target
    int*    s_ent  = s_tgt + PRE;               // PRE*SLOTS creators (asc)

    __shared__ int s_off[NC + 1], s_toff[NC + 1];
    __shared__ int s_wcnt[NWP][NC], s_wbase[NWP][NC];
    __shared__ int m_t[MAXP], m_tgt[MAXP];
    __shared__ int s_uniq[NC][MAXU];
    __shared__ int s_mm[NC][MAXM];
    __shared__ float4 s_pfxm[NC][MAXM + 1];     // prefix means
    __shared__ float  s_pfxa[NC][MAXM + 1];     // prefix areas
    __shared__ int s_np, s_changed, s_dirty;

    const int tid  = threadIdx.x;
    const int wrp  = tid >> 5;
    const int lane = tid & 31;
    const unsigned lt = (1u << lane) - 1u;

    // ---- parallel stable class bucketing (16 warps, chunked) ----
    {
        const int beg = wrp * CHUNK, end = beg + CHUNK;
        int cnt[NC];
        #pragma unroll
        for (int c = 0; c < NC; c++) cnt[c] = 0;
        for (int g = beg; g < end; g += 32) {
            const int i = g + lane;
            const int ci = (i < end) ? (int)x[i * 6 + 5] : -1;
            #pragma unroll
            for (int c = 0; c < NC; c++)
                cnt[c] += __popc(__ballot_sync(FULL, ci == c));
        }
        if (lane == 0)
            #pragma unroll
            for (int c = 0; c < NC; c++) s_wcnt[wrp][c] = cnt[c];
        __syncthreads();
        if (tid == 0) {
            int off = 0, tt = 0;
            for (int c = 0; c < NC; c++) {
                s_off[c] = off;
                s_toff[c] = tt;
                int run = 0;
                for (int w = 0; w < NWP; w++) {
                    s_wbase[w][c] = off + run;
                    run += s_wcnt[w][c];
                }
                off += run;
                tt += (run + 31) >> 5;
            }
            s_off[NC] = off;    // == PRE
            s_toff[NC] = tt;    // total tiles
        }
        __syncthreads();
        int run[NC];
        #pragma unroll
        for (int c = 0; c < NC; c++) run[c] = 0;
        for (int g = beg; g < end; g += 32) {
            const int i = g + lane;
            const int ci = (i < end) ? (int)x[i * 6 + 5] : -1;
            #pragma unroll
            for (int c = 0; c < NC; c++) {
                const unsigned b = __ballot_sync(FULL, ci == c);
                if (ci == c)
                    d_det[s_wbase[wrp][c] + run[c] + __popc(b & lt)] = i;
                run[c] += __popc(b);
            }
        }
    }
    __syncthreads();

    // ---- dense init: singleton clusters (reference-exact) ----
    for (int k = tid; k < PRE; k += T) {
        const int i = d_det[k];
        const float* d = x + i * 6;
        const float b0 = d[0], b1 = d[1], b2 = d[2], b3 = d[3], s = d[4];
        d_boxv[k] = make_float4(b0, b1, b2, b3);
        d_a1[k]   = __fmul_rn(__fsub_rn(b2, b0), __fsub_rn(b3, b1));
        d_scr[k]  = s;
        d_ss[k] = s; d_cnt[k] = 1;
        float4 m;
        m.x = __fdiv_rn(__fmul_rn(s, b0), s);
        m.y = __fdiv_rn(__fmul_rn(s, b1), s);
        m.z = __fdiv_rn(__fmul_rn(s, b2), s);
        m.w = __fdiv_rn(__fmul_rn(s, b3), s);
        d_mean[k] = m;
        d_area[k] = __fmul_rn(__fsub_rn(m.z, m.x), __fsub_rn(m.w, m.y));
        s_pos[i] = k;
    }
    __syncthreads();

    // ---- phase 1: all same-class pairs vs singleton means (flat tiles) ----
    for (int w = wrp; w < s_toff[NC]; w += NWP) {
        int c = 0;
        while (c + 1 < NC && s_toff[c + 1] <= w) c++;
        const int tile = w - s_toff[c];
        const int off = s_off[c], n = s_off[c + 1] - off;
        const int bi = tile * 32 + lane;
        const bool act = bi < n;
        float4 bb = make_float4(0.f, 0.f, 0.f, 0.f);
        float a1 = 0.f; int bdet = 0;
        if (act) {
            bb = d_boxv[off + bi];
            a1 = d_a1[off + bi];
            bdet = d_det[off + bi];
        }
        int ne = 0;
        const int hi = min(n, tile * 32 + 32);
        #pragma unroll 4
        for (int ai = 0; ai < hi; ai++) {
            const float4 mm = d_mean[off + ai];   // broadcast LDS
            const float  a2 = d_area[off + ai];
            if (act && ai < bi &&
                iou_match(bb.x, bb.y, bb.z, bb.w, a1,
                          mm.x, mm.y, mm.z, mm.w, a2)) {
                if (ne < SLOTS) s_ent[bdet * SLOTS + ne] = d_det[off + ai];
                ne++;                            // ascending creator order
            }
        }
        if (act) {
            s_nent[bdet] = (ne > SLOTS) ? OVF : ne;
            s_stat[bdet] = (ne > 0) ? 0 : 1;
        }
    }
    __syncthreads();

    // ---- outer resolve/validate loop ----
    for (int it = 0; it < 24; it++) {
        // -- resolve fixpoint (rounds <= dependency depth) --
        while (true) {
            if (tid == 0) s_changed = 0;
            __syncthreads();
            for (int i = tid; i < PRE; i += T) {
                if (s_stat[i] != 0) continue;
                const int ne = s_nent[i];
                int res = 1, tgt = -1;
                if (ne == OVF) {
                    const int p = s_pos[i];
                    int c = 0;
                    while (c + 1 < NC && s_off[c + 1] <= p) c++;
                    const float4 bb = d_boxv[p];
                    const float a1 = d_a1[p];
                    for (int k = s_off[c]; k < p; k++) {
                        const int a = d_det[k];
                        const int st = s_stat[a];
                        if (st == 0) { res = 0; break; }
                        if (st == 1) {
                            const float4 mm = d_mean[k];
                            if (iou_match(bb.x, bb.y, bb.z, bb.w, a1,
                                          mm.x, mm.y, mm.z, mm.w, d_area[k])) {
                                res = 2; tgt = a; break;
                            }
                        }
                    }
                } else {
                    for (int e = 0; e < ne; e++) {
                        const int a = s_ent[i * SLOTS + e];
                        const int st = s_stat[a];
                        if (st == 0) { res = 0; break; }
                        if (st == 1) { res = 2; tgt = a; break; }
                    }
                }
                if (res == 1) { s_stat[i] = 1; s_changed = 1; }
                else if (res == 2) { s_tgt[i] = tgt; s_stat[i] = 2; s_changed = 1; }
            }
            __syncthreads();
            if (!s_changed) break;
        }

        // -- collect merge pairs --
        if (tid == 0) { s_np = 0; s_dirty = 0; }
        __syncthreads();
        for (int i = tid; i < PRE; i += T)
            if (s_stat[i] == 2) {
                const int j = atomicAdd(&s_np, 1);
                if (j < MAXP) { m_t[j] = i; m_tgt[j] = s_tgt[i]; }
            }
        __syncthreads();
        const int np = min(s_np, MAXP);
        if (np == 0) break;   // no merges at all: singleton state is final

        // -- global re-init to singleton state --
        for (int k = tid; k < PRE; k += T) {
            const float4 b = d_boxv[k];
            const float s = d_scr[k];
            d_ss[k] = s; d_cnt[k] = 1;
            float4 m;
            m.x = __fdiv_rn(__fmul_rn(s, b.x), s);
            m.y = __fdiv_rn(__fmul_rn(s, b.y), s);
            m.z = __fdiv_rn(__fmul_rn(s, b.z), s);
            m.w = __fdiv_rn(__fmul_rn(s, b.w), s);
            d_mean[k] = m;
            d_area[k] = __fmul_rn(__fsub_rn(m.z, m.x), __fsub_rn(m.w, m.y));
        }
        __syncthreads();

        // -- per-class build + validate (warp c handles class c) --
        if (wrp < NC) {
            const int c = wrp;
            const int cBeg = s_off[c], cEnd = s_off[c + 1];

            // unique flagged clusters of this class
            int nu = 0;
            for (int j0 = 0; j0 < np; j0 += 32) {
                const int j = j0 + lane;
                bool take = false; int a = -1;
                if (j < np) {
                    a = m_tgt[j];
                    const int pa = s_pos[a];
                    if (pa >= cBeg && pa < cEnd) {
                        take = true;
                        for (int j2 = 0; j2 < j; j2++)
                            if (m_tgt[j2] == a) { take = false; break; }
                    }
                }
                const unsigned b = __ballot_sync(FULL, take);
                if (take) {
                    const int idx = nu + __popc(b & lt);
                    if (idx < MAXU) s_uniq[c][idx] = a;
                }
                nu += __popc(b);
            }
            nu = min(nu, MAXU);

            for (int ui = 0; ui < nu; ui++) {
                const int a = s_uniq[c][ui];
                const int p = s_pos[a];

                // gather this cluster's merges
                int nm = 0;
                for (int j0 = 0; j0 < np; j0 += 32) {
                    const int j = j0 + lane;
                    const bool take = (j < np) && (m_tgt[j] == a);
                    const unsigned b = __ballot_sync(FULL, take);
                    if (take) {
                        const int idx = nm + __popc(b & lt);
                        if (idx < MAXM) s_mm[c][idx] = m_t[j];
                    }
                    nm += __popc(b);
                }
                nm = min(nm, MAXM);
                __syncwarp();

                // sort merges ascending (lane 0; nm is tiny)
                if (lane == 0) {
                    for (int e = 1; e < nm; e++) {
                        const int v = s_mm[c][e];
                        int f = e - 1;
                        while (f >= 0 && s_mm[c][f] > v) {
                            s_mm[c][f + 1] = s_mm[c][f]; f--;
                        }
                        s_mm[c][f + 1] = v;
                    }
                }
                __syncwarp();

                // prefix states: lane e computes state after e merges
                // (reference-exact ascending chain; merge-j loads broadcast)
                const float4 ab = d_boxv[p];
                const float as = d_scr[p];
                float hx1 = CUDART_INF_F, hy1 = CUDART_INF_F;
                float hx2 = -CUDART_INF_F, hy2 = -CUDART_INF_F;
                if (lane >= 1 && lane <= nm) {
                    float swx = __fmul_rn(as, ab.x), swy = __fmul_rn(as, ab.y);
                    float swz = __fmul_rn(as, ab.z), sww = __fmul_rn(as, ab.w);
                    float ss = as;
                    for (int j = 0; j < lane; j++) {
                        const int pm = s_pos[s_mm[c][j]];
                        const float4 bm = d_boxv[pm];
                        const float sm = d_scr[pm];
                        swx = __fadd_rn(swx, __fmul_rn(sm, bm.x));
                        swy = __fadd_rn(swy, __fmul_rn(sm, bm.y));
                        swz = __fadd_rn(swz, __fmul_rn(sm, bm.z));
                        sww = __fadd_rn(sww, __fmul_rn(sm, bm.w));
                        ss = __fadd_rn(ss, sm);
                    }
                    float4 m;
                    m.x = __fdiv_rn(swx, ss); m.y = __fdiv_rn(swy, ss);
                    m.z = __fdiv_rn(swz, ss); m.w = __fdiv_rn(sww, ss);
                    s_pfxm[c][lane] = m;
                    s_pfxa[c][lane] = __fmul_rn(__fsub_rn(m.z, m.x),
                                                __fsub_rn(m.w, m.y));
                    hx1 = m.x; hy1 = m.y; hx2 = m.z; hy2 = m.w;
                    if (lane == nm) {   // final cluster state
                        d_mean[p] = m;
                        d_area[p] = s_pfxa[c][lane];
                        d_ss[p] = ss;
                        d_cnt[p] = nm + 1;
                    }
                }
                // hull of states 1..nm (warp reduction)
                #pragma unroll
                for (int d = 16; d > 0; d >>= 1) {
                    hx1 = fminf(hx1, __shfl_xor_sync(FULL, hx1, d));
                    hy1 = fminf(hy1, __shfl_xor_sync(FULL, hy1, d));
                    hx2 = fmaxf(hx2, __shfl_xor_sync(FULL, hx2, d));
                    hy2 = fmaxf(hy2, __shfl_xor_sync(FULL, hy2, d));
                }
                __syncwarp();

                // validate later same-class dets vs time-correct prefixes
                const int kStart = s_pos[s_mm[c][0]] + 1;
                for (int k = kStart + lane; k < cEnd; k += 32) {
                    const int tu = d_det[k];
                    const int ne = s_nent[tu];
                    if (ne == OVF) continue;        // ovf dets rescan anyway
                    const float4 ub = d_boxv[k];
                    // hull prune: no overlap -> no state can match
                    const bool overlap =
                        (fminf(ub.z, hx2) > fmaxf(ub.x, hx1)) &&
                        (fminf(ub.w, hy2) > fmaxf(ub.y, hy1));
                    int fe = -1;
                    for (int e = 0; e < ne; e++)
                        if (s_ent[tu * SLOTS + e] == a) { fe = e; break; }
                    bool match = false;
                    if (overlap) {
                        int e = 1;                    // #(merges with id < tu)
                        while (e < nm && s_mm[c][e] < tu) e++;
                        const float4 mm = s_pfxm[c][e];
                        match = iou_match(ub.x, ub.y, ub.z, ub.w, d_a1[k],
                                          mm.x, mm.y, mm.z, mm.w, s_pfxa[c][e]);
                    }
                    if (match && fe < 0) {
                        if (ne < SLOTS) {
                            int ip = ne;
                            for (int e = 0; e < ne; e++)
                                if (s_ent[tu * SLOTS + e] > a) { ip = e; break; }
                            for (int e = ne; e > ip; e--)
                                s_ent[tu * SLOTS + e] = s_ent[tu * SLOTS + e - 1];
                            s_ent[tu * SLOTS + ip] = a;
                            s_nent[tu] = ne + 1;
                        } else s_nent[tu] = OVF;
                        s_dirty = 1;
                    } else if (!match && fe >= 0) {
                        for (int e = fe; e < ne - 1; e++)
                            s_ent[tu * SLOTS + e] = s_ent[tu * SLOTS + e + 1];
                        s_nent[tu] = ne - 1;
                        s_dirty = 1;
                    }
                }
                __syncwarp();
            }
        }
        __syncthreads();
        if (!s_dirty) break;

        // lists changed: reset statuses and re-resolve
        for (int i = tid; i < PRE; i += T)
            s_stat[i] = (s_nent[i] > 0) ? 0 : 1;
        __syncthreads();
    }
    __syncthreads();

    // ---- export (det-indexed keys; alive order == reference order) ----
    for (int k = tid; k < PRE; k += T) {
        const int i = d_det[k];
        if (s_stat[i] != 2) {
            int c = 0;
            while (c + 1 < NC && s_off[c + 1] <= k) c++;
            const float4 m = d_mean[k];
            g_box[i * 4 + 0] = m.x;
            g_box[i * 4 + 1] = m.y;
            g_box[i * 4 + 2] = m.z;
            g_box[i * 4 + 3] = m.w;
            const float scv = __fdiv_rn(d_ss[k], fmaxf((float)d_cnt[k], 1.0f));
            g_score[i] = scv;
            g_cls[i]   = (float)c;
            g_key[i]   = scv;          // valid keys >= 0.05
        } else {
            g_key[i] = -1.0f;          // invalid sentinel (matches reference)
        }
        g_rank[i] = 0;
    }
}

// ---------------------------------------------------------------------------
// Kernel 2: partial stable-descending ranks (8 j-blocks x 8 i-chunks)
// ---------------------------------------------------------------------------
__global__ void wbf_rank_part() {
    __shared__ float kk[ICH];
    const int i0 = blockIdx.y * ICH;
    for (int i = threadIdx.x; i < ICH; i += blockDim.x) kk[i] = g_key[i0 + i];
    __syncthreads();

    const int j = blockIdx.x * blockDim.x + threadIdx.x;
    if (j >= PRE) return;
    const float kj = g_key[j];
    int r = 0;
    #pragma unroll 10
    for (int ii = 0; ii < ICH; ii++) {
        const float ki = kk[ii];
        const int i = i0 + ii;
        r += (ki > kj) || (ki == kj && i < j);
    }
    if (r) atomicAdd(&g_rank[j], r);
}

// ---------------------------------------------------------------------------
// Kernel 3: scatter (ranks are a permutation -> each row written once)
// ---------------------------------------------------------------------------
__global__ void wbf_scatter(float* __restrict__ out) {
    const int j = blockIdx.x * blockDim.x + threadIdx.x;
    if (j >= PRE) return;
    const int r = g_rank[j];
    if (r < POST) {
        float* row = out + r * 6;
        if (g_key[j] >= 0.0f) {
            row[0] = g_box[j * 4 + 0];
            row[1] = g_box[j * 4 + 1];
            row[2] = g_box[j * 4 + 2];
            row[3] = g_box[j * 4 + 3];
            row[4] = g_score[j];
            row[5] = g_cls[j];
        } else {
            row[0] = 0.f; row[1] = 0.f; row[2] = 0.f;
            row[3] = 0.f; row[4] = 0.f; row[5] = 0.f;
        }
    }
}

// ---------------------------------------------------------------------------

static const int SCAN_SMEM_BYTES =
    PRE * (int)sizeof(float4) * 2 +       // d_boxv + d_mean
    PRE * (int)sizeof(float) * 4 +        // d_area + d_a1 + d_ss + d_scr
    PRE * (int)sizeof(int) * 6 +          // d_cnt d_det s_pos s_nent s_stat s_tgt
    PRE * SLOTS * (int)sizeof(int);       // s_ent

extern "C" void kernel_launch(void* const* d_in, const int* in_sizes, int n_in,
                              void* d_out, int out_size) {
    const float* x = (const float*)d_in[0];
    float* out = (float*)d_out;

    cudaFuncSetAttribute(wbf_scan,
                         cudaFuncAttributeMaxDynamicSharedMemorySize,
                         SCAN_SMEM_BYTES);

    wbf_scan<<<1, T, SCAN_SMEM_BYTES>>>(x);
    wbf_rank_part<<<dim3(8, 8), 256>>>();
    wbf_scatter<<<8, 256>>>(out);
}